// round 9
// baseline (speedup 1.0000x reference)
#include <cuda_runtime.h>
#include <cuda_bf16.h>
#include <cuda_fp16.h>
#include <math.h>
#include <stdint.h>

#define HEADS    16
#define DH       64
#define NSEQ     2048
#define BATCH    4
#define DIMIN    1024
#define HID      1024
#define ROWS     (BATCH*NSEQ)     // 8192
#define QKV_COLS (3*HID)          // 3072
#define BH       (BATCH*HEADS)    // 64
#define ATT_SCALE 0.125f
#define LDK      40               // padded k-stride (2B elems)
#define NITILE   (NSEQ/128)       // 16

// ---------------- static scratch ----------------
__device__ float g_qkv[(size_t)ROWS * QKV_COLS];            // fp32 (only V third written)
__device__ float g_rl[BH * NSEQ];                           // 1/colsum
__device__ float g_pcs[(size_t)BH * NITILE * NSEQ];         // partial col sums
__device__ __half g_P [(size_t)BH * NSEQ * NSEQ];           // P = exp(s), fp16 (537MB)
__device__ __nv_bfloat16 g_xh [(size_t)ROWS * DIMIN];
__device__ __nv_bfloat16 g_xl [(size_t)ROWS * DIMIN];
__device__ __nv_bfloat16 g_qkvh[(size_t)ROWS * QKV_COLS];   // only Q,K thirds used
__device__ __nv_bfloat16 g_qkvl[(size_t)ROWS * QKV_COLS];
__device__ __nv_bfloat16 g_wqh[(size_t)QKV_COLS * DIMIN];   // w_qkv^T hi  [N,K]
__device__ __nv_bfloat16 g_wql[(size_t)QKV_COLS * DIMIN];
__device__ __nv_bfloat16 g_woh[(size_t)DIMIN * HID];        // w_out^T hi  [N,K]
__device__ __nv_bfloat16 g_wol[(size_t)DIMIN * HID];
__device__ __nv_bfloat16 g_yh [(size_t)ROWS * HID];
__device__ __nv_bfloat16 g_yl [(size_t)ROWS * HID];

// ---------------- helpers ----------------
__device__ __forceinline__ uint32_t smem_u32(const void* p) {
    uint32_t a;
    asm("{ .reg .u64 t; cvta.to.shared.u64 t, %1; cvt.u32.u64 %0, t; }"
        : "=r"(a) : "l"(p));
    return a;
}
__device__ __forceinline__ void cp_async16(uint32_t s, const void* g) {
    asm volatile("cp.async.cg.shared.global [%0], [%1], 16;" :: "r"(s), "l"(g));
}
#define CP_COMMIT() asm volatile("cp.async.commit_group;" ::: "memory")
template <int N>
__device__ __forceinline__ void cp_wait() {
    asm volatile("cp.async.wait_group %0;" :: "n"(N) : "memory");
}
#define LDM_X4(r, a)                                                        \
    asm volatile("ldmatrix.sync.aligned.m8n8.x4.shared.b16 {%0,%1,%2,%3}, [%4];" \
        : "=r"((r)[0]), "=r"((r)[1]), "=r"((r)[2]), "=r"((r)[3]) : "r"(a))

// mma.sync m16n8k16 bf16: D += A*B  (acc fp32)
__device__ __forceinline__ void mma_bf(float* c, const uint32_t* a,
                                       uint32_t b0, uint32_t b1) {
    asm volatile(
        "mma.sync.aligned.m16n8k16.row.col.f32.bf16.bf16.f32 "
        "{%0,%1,%2,%3}, {%4,%5,%6,%7}, {%8,%9}, {%0,%1,%2,%3};\n"
        : "+f"(c[0]), "+f"(c[1]), "+f"(c[2]), "+f"(c[3])
        : "r"(a[0]), "r"(a[1]), "r"(a[2]), "r"(a[3]), "r"(b0), "r"(b1));
}
// mma.sync m16n8k16 fp16: D += A*B  (acc fp32)
__device__ __forceinline__ void mma_f16(float* c, const uint32_t* a,
                                        uint32_t b0, uint32_t b1) {
    asm volatile(
        "mma.sync.aligned.m16n8k16.row.col.f32.f16.f16.f32 "
        "{%0,%1,%2,%3}, {%4,%5,%6,%7}, {%8,%9}, {%0,%1,%2,%3};\n"
        : "+f"(c[0]), "+f"(c[1]), "+f"(c[2]), "+f"(c[3])
        : "r"(a[0]), "r"(a[1]), "r"(a[2]), "r"(a[3]), "r"(b0), "r"(b1));
}

__device__ __forceinline__ void split2(float a, float b,
                                       __nv_bfloat162& hp, __nv_bfloat162& lp) {
    __nv_bfloat16 ha = __float2bfloat16(a), hb = __float2bfloat16(b);
    hp.x = ha; hp.y = hb;
    lp.x = __float2bfloat16(a - __bfloat162float(ha));
    lp.y = __float2bfloat16(b - __bfloat162float(hb));
}

// stage layout (bytes): Ah 0 | Al 10240 | Bh 20480 | Bl 30720 ; stage 40960
#define STG 40960
#define DSMEM (2*STG)

__device__ __forceinline__ void stage_load(uint32_t sbase,
    const __nv_bfloat16* Ah, const __nv_bfloat16* Al, int sA,
    const __nv_bfloat16* Bh, const __nv_bfloat16* Bl, int sB,
    int k0, int tid)
{
#pragma unroll
    for (int r = 0; r < 2; r++) {
        int sid = tid + (r << 8);
        int row = sid >> 2, seg = sid & 3;
        uint32_t so = sbase + (uint32_t)(row * (LDK * 2) + seg * 16);
        size_t oa = (size_t)row * sA + k0 + seg * 8;
        size_t ob = (size_t)row * sB + k0 + seg * 8;
        cp_async16(so,          Ah + oa);
        cp_async16(so + 10240u, Al + oa);
        cp_async16(so + 20480u, Bh + ob);
        cp_async16(so + 30720u, Bl + ob);
    }
}

// 3-pass bf16 compute of one 32-k chunk; warp tile 32(m) x 64(n).
// Pass-major inner ordering: 4 independent accumulator chains between
// any reuse of the same acc (HMMA RAW-latency cover). Per-acc accumulation
// order (HH, HL, LH per ks) is unchanged -> numerically identical.
__device__ __forceinline__ void mma_chunk3(uint32_t sb, int warp_m, int warp_n,
                                           uint32_t ldm_off, float acc[2][8][4]) {
    const uint32_t bAh = sb, bAl = sb + 10240, bBh = sb + 20480, bBl = sb + 30720;
#pragma unroll
    for (int ks = 0; ks < 32; ks += 16) {
        uint32_t aH[2][4], aL[2][4];
#pragma unroll
        for (int mt = 0; mt < 2; mt++) {
            uint32_t ro = (uint32_t)((warp_m * 32 + mt * 16) * LDK + ks) * 2 + ldm_off;
            LDM_X4(aH[mt], bAh + ro);
            LDM_X4(aL[mt], bAl + ro);
        }
#pragma unroll
        for (int c = 0; c < 4; c++) {
            uint32_t bh[4], bl[4];
            uint32_t ro = (uint32_t)((warp_n * 64 + c * 16) * LDK + ks) * 2 + ldm_off;
            LDM_X4(bh, bBh + ro);
            LDM_X4(bl, bBl + ro);
            // pass HH
#pragma unroll
            for (int mt = 0; mt < 2; mt++)
#pragma unroll
                for (int half = 0; half < 2; half++)
                    mma_bf(acc[mt][c * 2 + half], aH[mt], bh[half], bh[half + 2]);
            // pass HL
#pragma unroll
            for (int mt = 0; mt < 2; mt++)
#pragma unroll
                for (int half = 0; half < 2; half++)
                    mma_bf(acc[mt][c * 2 + half], aH[mt], bl[half], bl[half + 2]);
            // pass LH
#pragma unroll
            for (int mt = 0; mt < 2; mt++)
#pragma unroll
                for (int half = 0; half < 2; half++)
                    mma_bf(acc[mt][c * 2 + half], aL[mt], bh[half], bh[half + 2]);
        }
    }
}

// =====================================================================
// projections: C[M,N] = (Ah+Al)[M,K] @ ((Bh+Bl)[N,K])^T
// QKV_MODE: Q/K tiles (bn<2*HID) -> write bf16 hi/lo; V tiles -> write fp32.
// =====================================================================
template <bool HAS_BIAS, bool QKV_MODE>
__global__ __launch_bounds__(256, 2) void mma_gemm(
    const __nv_bfloat16* __restrict__ Ah, const __nv_bfloat16* __restrict__ Al,
    const __nv_bfloat16* __restrict__ Bh, const __nv_bfloat16* __restrict__ Bl,
    const float* __restrict__ bias, float* __restrict__ C,
    __nv_bfloat16* __restrict__ Ch, __nv_bfloat16* __restrict__ Cl,
    int M, int N, int K)
{
    extern __shared__ char smem[];
    const uint32_t sb32 = smem_u32(smem);
    const int tid = threadIdx.x, lane = tid & 31, wid = tid >> 5;
    const int warp_m = wid & 3, warp_n = wid >> 2;
    const int g = lane >> 2, ti = lane & 3;
    const uint32_t ldm_off =
        (uint32_t)((((lane >> 3) & 1) * 8 + (lane & 7)) * LDK + ((lane >> 4) * 8)) * 2;
    const int bm = blockIdx.y * 128, bn = blockIdx.x * 128;

    const __nv_bfloat16* Ah0 = Ah + (size_t)bm * K;
    const __nv_bfloat16* Al0 = Al + (size_t)bm * K;
    const __nv_bfloat16* Bh0 = Bh + (size_t)bn * K;
    const __nv_bfloat16* Bl0 = Bl + (size_t)bn * K;

    float acc[2][8][4] = {};
    const int NT = K >> 5;

    stage_load(sb32, Ah0, Al0, K, Bh0, Bl0, K, 0, tid);
    CP_COMMIT();
    for (int kt = 0; kt < NT; kt++) {
        if (kt + 1 < NT) {
            stage_load(sb32 + ((kt + 1) & 1) * STG, Ah0, Al0, K, Bh0, Bl0, K,
                       (kt + 1) << 5, tid);
            CP_COMMIT();
            cp_wait<1>();
        } else {
            cp_wait<0>();
        }
        __syncthreads();
        mma_chunk3(sb32 + (kt & 1) * STG, warp_m, warp_n, ldm_off, acc);
        __syncthreads();
    }

    const bool isV = QKV_MODE && (bn >= 2 * HID);
#pragma unroll
    for (int mt = 0; mt < 2; mt++) {
        int r0 = bm + warp_m * 32 + mt * 16 + g;
#pragma unroll
        for (int nt = 0; nt < 8; nt++) {
            int col = bn + warp_n * 64 + nt * 8 + ti * 2;
            float v0 = acc[mt][nt][0], v1 = acc[mt][nt][1];
            float v2 = acc[mt][nt][2], v3 = acc[mt][nt][3];
            if (HAS_BIAS) {
                float2 bb = *(const float2*)(bias + col);
                v0 += bb.x; v1 += bb.y; v2 += bb.x; v3 += bb.y;
            }
            if (!QKV_MODE || isV) {
                *(float2*)(C + (size_t)r0 * N + col)       = make_float2(v0, v1);
                *(float2*)(C + (size_t)(r0 + 8) * N + col) = make_float2(v2, v3);
            }
            if (QKV_MODE && !isV) {
                __nv_bfloat162 hp, lp;
                split2(v0, v1, hp, lp);
                *(__nv_bfloat162*)(Ch + (size_t)r0 * N + col) = hp;
                *(__nv_bfloat162*)(Cl + (size_t)r0 * N + col) = lp;
                split2(v2, v3, hp, lp);
                *(__nv_bfloat162*)(Ch + (size_t)(r0 + 8) * N + col) = hp;
                *(__nv_bfloat162*)(Cl + (size_t)(r0 + 8) * N + col) = lp;
            }
        }
    }
}

// =====================================================================
// scores: P = exp(scale*q.k) -> fp16; also per-tile column partial sums
// =====================================================================
__global__ __launch_bounds__(256, 2) void scores_mma() {
    extern __shared__ char smem[];
    const uint32_t sb32 = smem_u32(smem);
    const int tid = threadIdx.x, lane = tid & 31, wid = tid >> 5;
    const int warp_m = wid & 3, warp_n = wid >> 2;
    const int g = lane >> 2, ti = lane & 3;
    const uint32_t ldm_off =
        (uint32_t)((((lane >> 3) & 1) * 8 + (lane & 7)) * LDK + ((lane >> 4) * 8)) * 2;

    const int bh = blockIdx.z;
    const int b = bh >> 4, h = bh & 15;
    const int i0 = blockIdx.y * 128;
    const int j0 = blockIdx.x * 128;

    const size_t qoff = (size_t)(b * NSEQ) * QKV_COLS + h * DH;
    const __nv_bfloat16* Qh = g_qkvh + qoff + (size_t)i0 * QKV_COLS;
    const __nv_bfloat16* Ql = g_qkvl + qoff + (size_t)i0 * QKV_COLS;
    const __nv_bfloat16* Kh = g_qkvh + qoff + HID + (size_t)j0 * QKV_COLS;
    const __nv_bfloat16* Kl = g_qkvl + qoff + HID + (size_t)j0 * QKV_COLS;

    float acc[2][8][4] = {};

    stage_load(sb32, Qh, Ql, QKV_COLS, Kh, Kl, QKV_COLS, 0, tid);
    CP_COMMIT();
#pragma unroll
    for (int kt = 0; kt < 2; kt++) {
        if (kt == 0) {
            stage_load(sb32 + STG, Qh, Ql, QKV_COLS, Kh, Kl, QKV_COLS, 32, tid);
            CP_COMMIT();
            cp_wait<1>();
        } else {
            cp_wait<0>();
        }
        __syncthreads();
        mma_chunk3(sb32 + kt * STG, warp_m, warp_n, ldm_off, acc);
        __syncthreads();
    }

    __half* P = g_P + (size_t)bh * NSEQ * NSEQ;
    float cs[8][2];
#pragma unroll
    for (int nt = 0; nt < 8; nt++) { cs[nt][0] = 0.f; cs[nt][1] = 0.f; }

#pragma unroll
    for (int mt = 0; mt < 2; mt++) {
        int r0 = i0 + warp_m * 32 + mt * 16 + g;
#pragma unroll
        for (int nt = 0; nt < 8; nt++) {
            int col = j0 + warp_n * 64 + nt * 8 + ti * 2;
            __half h0 = __float2half(__expf(acc[mt][nt][0] * ATT_SCALE));
            __half h1 = __float2half(__expf(acc[mt][nt][1] * ATT_SCALE));
            __half h2 = __float2half(__expf(acc[mt][nt][2] * ATT_SCALE));
            __half h3 = __float2half(__expf(acc[mt][nt][3] * ATT_SCALE));
            // sum the ROUNDED values so the softmax ratio partially cancels
            cs[nt][0] += __half2float(h0) + __half2float(h2);
            cs[nt][1] += __half2float(h1) + __half2float(h3);
            __half2 w0; w0.x = h0; w0.y = h1;
            __half2 w1; w1.x = h2; w1.y = h3;
            *(__half2*)(P + (size_t)r0 * NSEQ + col)       = w0;
            *(__half2*)(P + (size_t)(r0 + 8) * NSEQ + col) = w1;
        }
    }

    // butterfly over g-lanes -> column sums over warp's 32 rows
#pragma unroll
    for (int nt = 0; nt < 8; nt++) {
#pragma unroll
        for (int e = 0; e < 2; e++) {
            float v = cs[nt][e];
            v += __shfl_xor_sync(0xFFFFFFFF, v, 4);
            v += __shfl_xor_sync(0xFFFFFFFF, v, 8);
            v += __shfl_xor_sync(0xFFFFFFFF, v, 16);
            cs[nt][e] = v;
        }
    }
    float* spart = (float*)smem;          // stage smem is free now
    if (g == 0) {
#pragma unroll
        for (int nt = 0; nt < 8; nt++) {
            spart[warp_m * 128 + warp_n * 64 + nt * 8 + ti * 2]     = cs[nt][0];
            spart[warp_m * 128 + warp_n * 64 + nt * 8 + ti * 2 + 1] = cs[nt][1];
        }
    }
    __syncthreads();
    if (tid < 128) {
        float s = spart[tid] + spart[128 + tid] + spart[256 + tid] + spart[384 + tid];
        g_pcs[((size_t)bh * NITILE + blockIdx.y) * NSEQ + j0 + tid] = s;
    }
}

// =====================================================================
// rsum: rl[bh][j] = 1 / sum_itile pcs
// =====================================================================
__global__ void rsum_kernel() {
    const int bh = blockIdx.y;
    const int j = blockIdx.x * 256 + threadIdx.x;
    const float* p = g_pcs + (size_t)bh * NITILE * NSEQ + j;
    float s = 0.f;
#pragma unroll
    for (int t = 0; t < NITILE; t++) s += p[(size_t)t * NSEQ];
    g_rl[bh * NSEQ + j] = 1.0f / s;
}

// =====================================================================
// av: Y = P_fp16 @ diag(rl) (Vh+Vl)   2-pass fp16 (V split exact).
// CTA tile 128(i) x 64(d), warp tile 16 x 64, k(j) chunk 32.
// Pass-major over c-pairs: 4 independent acc chains.
// =====================================================================
__global__ __launch_bounds__(256, 2) void av_mma() {
    __shared__ __align__(16) char sm[20480]; // P 10240 | Vh 5120 | Vl 5120
    const uint32_t smP  = smem_u32(sm);
    const uint32_t smVh = smP + 10240;
    const uint32_t smVl = smP + 15360;
    char* smVhc = sm + 10240;
    char* smVlc = sm + 15360;

    const int tid = threadIdx.x, lane = tid & 31, wid = tid >> 5;
    const int g = lane >> 2, ti = lane & 3;
    const uint32_t ldm_off =
        (uint32_t)((((lane >> 3) & 1) * 8 + (lane & 7)) * LDK + ((lane >> 4) * 8)) * 2;

    const int bh = blockIdx.y;
    const int b = bh >> 4, h = bh & 15;
    const int i0 = blockIdx.x * 128;

    const __half* Pg = g_P + (size_t)bh * NSEQ * NSEQ + (size_t)i0 * NSEQ;
    const float* Vbase = g_qkv + (size_t)(b * NSEQ) * QKV_COLS + 2 * HID + h * DH;
    const float* rl = g_rl + bh * NSEQ;

    const int jl = tid >> 3;            // 0..31  (V row)
    const int d0 = (tid & 7) * 8;       // V col group

    float acc[8][4] = {};

    for (int j0 = 0; j0 < NSEQ; j0 += 32) {
        // P tile via cp.async: 128 rows x 32 j
#pragma unroll
        for (int r = 0; r < 2; r++) {
            int sid = tid + (r << 8);
            int row = sid >> 2, seg = sid & 3;
            uint32_t so = (uint32_t)(row * (LDK * 2) + seg * 16);
            cp_async16(smP + so, Pg + (size_t)row * NSEQ + j0 + seg * 8);
        }
        CP_COMMIT();
        // V tile: fp32 load, *rl, transpose + fp16 hi/lo split into smem
        {
            const float inv = rl[j0 + jl];
            const float* Vr = Vbase + (size_t)(j0 + jl) * QKV_COLS + d0;
            float4 a = *(const float4*)Vr;
            float4 c = *(const float4*)(Vr + 4);
            float vv[8] = {a.x, a.y, a.z, a.w, c.x, c.y, c.z, c.w};
#pragma unroll
            for (int e = 0; e < 8; e++) {
                float val = vv[e] * inv;
                __half hi = __float2half(val);
                __half lo = __float2half(val - __half2float(hi));
                int off = ((d0 + e) * LDK + jl) * 2;
                *(__half*)(smVhc + off) = hi;
                *(__half*)(smVlc + off) = lo;
            }
        }
        cp_wait<0>();
        __syncthreads();

#pragma unroll
        for (int ks = 0; ks < 32; ks += 16) {
            uint32_t aP[4];
            uint32_t ro = (uint32_t)((wid * 16) * LDK + ks) * 2 + ldm_off;
            LDM_X4(aP, smP + ro);
#pragma unroll
            for (int c = 0; c < 4; c += 2) {
                uint32_t bhm[2][4], blm[2][4];
#pragma unroll
                for (int cc = 0; cc < 2; cc++) {
                    uint32_t rb = (uint32_t)(((c + cc) * 16) * LDK + ks) * 2 + ldm_off;
                    LDM_X4(bhm[cc], smVh + rb);
                    LDM_X4(blm[cc], smVl + rb);
                }
                // pass Vh: 4 independent chains
#pragma unroll
                for (int cc = 0; cc < 2; cc++)
#pragma unroll
                    for (int half = 0; half < 2; half++)
                        mma_f16(acc[(c + cc) * 2 + half], aP,
                                bhm[cc][half], bhm[cc][half + 2]);
                // pass Vl
#pragma unroll
                for (int cc = 0; cc < 2; cc++)
#pragma unroll
                    for (int half = 0; half < 2; half++)
                        mma_f16(acc[(c + cc) * 2 + half], aP,
                                blm[cc][half], blm[cc][half + 2]);
            }
        }
        __syncthreads();
    }

    // epilogue: write y hi/lo bf16
    const int irow = i0 + wid * 16 + g;
#pragma unroll
    for (int nt = 0; nt < 8; nt++) {
        int d = nt * 8 + ti * 2;
        size_t o0 = (size_t)(b * NSEQ + irow) * HID + h * DH + d;
        size_t o1 = (size_t)(b * NSEQ + irow + 8) * HID + h * DH + d;
        __nv_bfloat162 hp, lp;
        split2(acc[nt][0], acc[nt][1], hp, lp);
        *(__nv_bfloat162*)(g_yh + o0) = hp;
        *(__nv_bfloat162*)(g_yl + o0) = lp;
        split2(acc[nt][2], acc[nt][3], hp, lp);
        *(__nv_bfloat162*)(g_yh + o1) = hp;
        *(__nv_bfloat162*)(g_yl + o1) = lp;
    }
}

// =====================================================================
// split fp32 -> bf16 hi/lo (elementwise)
// =====================================================================
__global__ void split_kernel(const float* __restrict__ in,
                             __nv_bfloat16* __restrict__ hi,
                             __nv_bfloat16* __restrict__ lo, size_t n4) {
    size_t i = (size_t)blockIdx.x * blockDim.x + threadIdx.x;
    if (i >= n4) return;
    float4 v = ((const float4*)in)[i];
    __nv_bfloat162 hp0, hp1, lp0, lp1;
    split2(v.x, v.y, hp0, lp0);
    split2(v.z, v.w, hp1, lp1);
    ((__nv_bfloat162*)hi)[i * 2 + 0] = hp0;
    ((__nv_bfloat162*)hi)[i * 2 + 1] = hp1;
    ((__nv_bfloat162*)lo)[i * 2 + 0] = lp0;
    ((__nv_bfloat162*)lo)[i * 2 + 1] = lp1;
}

// =====================================================================
// transpose + split: w[K,N] fp32 -> th/tl [N,K] bf16
// =====================================================================
__global__ void transpose_split_kernel(const float* __restrict__ w,
                                       __nv_bfloat16* __restrict__ th,
                                       __nv_bfloat16* __restrict__ tl,
                                       int K, int N) {
    __shared__ float tile[32][33];
    const int k0 = blockIdx.y * 32;
    const int n0 = blockIdx.x * 32;
    const int tx = threadIdx.x, ty = threadIdx.y;   // (32,8)
#pragma unroll
    for (int r = 0; r < 4; r++)
        tile[ty + 8 * r][tx] = w[(size_t)(k0 + ty + 8 * r) * N + n0 + tx];
    __syncthreads();
#pragma unroll
    for (int r = 0; r < 4; r++) {
        const int n = n0 + ty + 8 * r;
        const int k = k0 + tx;
        float v = tile[tx][ty + 8 * r];
        __nv_bfloat16 hh = __float2bfloat16(v);
        th[(size_t)n * K + k] = hh;
        tl[(size_t)n * K + k] = __float2bfloat16(v - __bfloat162float(hh));
    }
}

// ---------------------------------------------------------------------
extern "C" void kernel_launch(void* const* d_in, const int* in_sizes, int n_in,
                              void* d_out, int out_size) {
    const float* x     = (const float*)d_in[0];
    const float* w_qkv = (const float*)d_in[1];
    const float* w_out = (const float*)d_in[2];
    const float* b_out = (const float*)d_in[3];
    float* out = (float*)d_out;

    cudaFuncSetAttribute(mma_gemm<false, true>,
                         cudaFuncAttributeMaxDynamicSharedMemorySize, DSMEM);
    cudaFuncSetAttribute(mma_gemm<true, false>,
                         cudaFuncAttributeMaxDynamicSharedMemorySize, DSMEM);
    cudaFuncSetAttribute(scores_mma,
                         cudaFuncAttributeMaxDynamicSharedMemorySize, DSMEM);

    void *p_qkv, *p_xh, *p_xl, *p_qh, *p_ql, *p_wqh, *p_wql, *p_woh, *p_wol,
         *p_yh, *p_yl;
    cudaGetSymbolAddress(&p_qkv, g_qkv);
    cudaGetSymbolAddress(&p_xh,  g_xh);
    cudaGetSymbolAddress(&p_xl,  g_xl);
    cudaGetSymbolAddress(&p_qh,  g_qkvh);
    cudaGetSymbolAddress(&p_ql,  g_qkvl);
    cudaGetSymbolAddress(&p_wqh, g_wqh);
    cudaGetSymbolAddress(&p_wql, g_wql);
    cudaGetSymbolAddress(&p_woh, g_woh);
    cudaGetSymbolAddress(&p_wol, g_wol);
    cudaGetSymbolAddress(&p_yh,  g_yh);
    cudaGetSymbolAddress(&p_yl,  g_yl);

    // 0a. split x -> bf16 hi/lo
    {
        size_t n4 = (size_t)ROWS * DIMIN / 4;
        split_kernel<<<(unsigned)((n4 + 255) / 256), 256>>>(
            x, (__nv_bfloat16*)p_xh, (__nv_bfloat16*)p_xl, n4);
    }
    // 0b/0c. transpose+split weights -> [N,K]
    transpose_split_kernel<<<dim3(QKV_COLS / 32, DIMIN / 32), dim3(32, 8)>>>(
        w_qkv, (__nv_bfloat16*)p_wqh, (__nv_bfloat16*)p_wql, DIMIN, QKV_COLS);
    transpose_split_kernel<<<dim3(HID / 32, DIMIN / 32), dim3(32, 8)>>>(
        w_out, (__nv_bfloat16*)p_woh, (__nv_bfloat16*)p_wol, DIMIN, HID);

    // 1. QKV projection: Q/K -> bf16 hi/lo, V -> fp32
    mma_gemm<false, true><<<dim3(QKV_COLS / 128, ROWS / 128), 256, DSMEM>>>(
        (const __nv_bfloat16*)p_xh, (const __nv_bfloat16*)p_xl,
        (const __nv_bfloat16*)p_wqh, (const __nv_bfloat16*)p_wql,
        nullptr, (float*)p_qkv,
        (__nv_bfloat16*)p_qh, (__nv_bfloat16*)p_ql,
        ROWS, QKV_COLS, DIMIN);

    // 2. P = exp(scale * Q K^T) (fp16) + partial column sums
    scores_mma<<<dim3(NSEQ / 128, NSEQ / 128, BH), 256, DSMEM>>>();

    // 3. rl = 1 / column sums (from partials)
    rsum_kernel<<<dim3(NSEQ / 256, BH), 256>>>();

    // 4. Y = P diag(rl) V  -> y hi/lo bf16
    av_mma<<<dim3(NSEQ / 128, BH), 256>>>();

    // 5. out = Y @ w_out + b_out
    mma_gemm<true, false><<<dim3(HID / 128, ROWS / 128), 256, DSMEM>>>(
        (const __nv_bfloat16*)p_yh, (const __nv_bfloat16*)p_yl,
        (const __nv_bfloat16*)p_woh, (const __nv_bfloat16*)p_wol,
        b_out, out, nullptr, nullptr, ROWS, HID, DIMIN);
}

// round 11
// speedup vs baseline: 1.1787x; 1.1787x over previous
#include <cuda_runtime.h>
#include <cuda_bf16.h>
#include <cuda_fp16.h>
#include <math.h>
#include <stdint.h>

#define HEADS    16
#define DH       64
#define NSEQ     2048
#define BATCH    4
#define DIMIN    1024
#define HID      1024
#define ROWS     (BATCH*NSEQ)     // 8192
#define QKV_COLS (3*HID)          // 3072
#define BH       (BATCH*HEADS)    // 64
#define ATT_SCALE 0.125f
#define LDK      40               // padded k-stride (2B elems)
#define NITILE   (NSEQ/128)       // 16

// ---------------- static scratch ----------------
__device__ float g_rl[BH * NSEQ];                           // 1/colsum
__device__ float g_pcs[(size_t)BH * NITILE * NSEQ];         // partial col sums
__device__ __half g_P [(size_t)BH * NSEQ * NSEQ];           // P = exp(s), fp16
__device__ __half g_v [(size_t)ROWS * HID];                 // V, fp16
__device__ __half g_y [(size_t)ROWS * HID];                 // attention out, fp16
__device__ __nv_bfloat16 g_xh [(size_t)ROWS * DIMIN];
__device__ __nv_bfloat16 g_xl [(size_t)ROWS * DIMIN];
__device__ __nv_bfloat16 g_qkvh[(size_t)ROWS * QKV_COLS];   // only Q,K thirds used
__device__ __nv_bfloat16 g_qkvl[(size_t)ROWS * QKV_COLS];
__device__ __nv_bfloat16 g_wqh[(size_t)QKV_COLS * DIMIN];   // w_qkv^T hi  [N,K]
__device__ __nv_bfloat16 g_wql[(size_t)QKV_COLS * DIMIN];
__device__ __half g_woh[(size_t)DIMIN * HID];               // w_out^T hi  [N,K] fp16
__device__ __half g_wol[(size_t)DIMIN * HID];               // w_out^T lo  fp16

// ---------------- helpers ----------------
__device__ __forceinline__ uint32_t smem_u32(const void* p) {
    uint32_t a;
    asm("{ .reg .u64 t; cvta.to.shared.u64 t, %1; cvt.u32.u64 %0, t; }"
        : "=r"(a) : "l"(p));
    return a;
}
__device__ __forceinline__ void cp_async16(uint32_t s, const void* g) {
    asm volatile("cp.async.cg.shared.global [%0], [%1], 16;" :: "r"(s), "l"(g));
}
#define CP_COMMIT() asm volatile("cp.async.commit_group;" ::: "memory")
template <int N>
__device__ __forceinline__ void cp_wait() {
    asm volatile("cp.async.wait_group %0;" :: "n"(N) : "memory");
}
#define LDM_X4(r, a)                                                        \
    asm volatile("ldmatrix.sync.aligned.m8n8.x4.shared.b16 {%0,%1,%2,%3}, [%4];" \
        : "=r"((r)[0]), "=r"((r)[1]), "=r"((r)[2]), "=r"((r)[3]) : "r"(a))

// mma.sync m16n8k16 bf16: D += A*B  (acc fp32)
__device__ __forceinline__ void mma_bf(float* c, const uint32_t* a,
                                       uint32_t b0, uint32_t b1) {
    asm volatile(
        "mma.sync.aligned.m16n8k16.row.col.f32.bf16.bf16.f32 "
        "{%0,%1,%2,%3}, {%4,%5,%6,%7}, {%8,%9}, {%0,%1,%2,%3};\n"
        : "+f"(c[0]), "+f"(c[1]), "+f"(c[2]), "+f"(c[3])
        : "r"(a[0]), "r"(a[1]), "r"(a[2]), "r"(a[3]), "r"(b0), "r"(b1));
}
// mma.sync m16n8k16 fp16: D += A*B  (acc fp32)
__device__ __forceinline__ void mma_f16(float* c, const uint32_t* a,
                                        uint32_t b0, uint32_t b1) {
    asm volatile(
        "mma.sync.aligned.m16n8k16.row.col.f32.f16.f16.f32 "
        "{%0,%1,%2,%3}, {%4,%5,%6,%7}, {%8,%9}, {%0,%1,%2,%3};\n"
        : "+f"(c[0]), "+f"(c[1]), "+f"(c[2]), "+f"(c[3])
        : "r"(a[0]), "r"(a[1]), "r"(a[2]), "r"(a[3]), "r"(b0), "r"(b1));
}

__device__ __forceinline__ void split2(float a, float b,
                                       __nv_bfloat162& hp, __nv_bfloat162& lp) {
    __nv_bfloat16 ha = __float2bfloat16(a), hb = __float2bfloat16(b);
    hp.x = ha; hp.y = hb;
    lp.x = __float2bfloat16(a - __bfloat162float(ha));
    lp.y = __float2bfloat16(b - __bfloat162float(hb));
}

// stage layout (bytes): Ah 0 | Al 10240 | Bh 20480 | Bl 30720 ; stage 40960
#define STG 40960
#define DSMEM (2*STG)

__device__ __forceinline__ void stage_load(uint32_t sbase,
    const __nv_bfloat16* Ah, const __nv_bfloat16* Al, int sA,
    const __nv_bfloat16* Bh, const __nv_bfloat16* Bl, int sB,
    int k0, int tid)
{
#pragma unroll
    for (int r = 0; r < 2; r++) {
        int sid = tid + (r << 8);
        int row = sid >> 2, seg = sid & 3;
        uint32_t so = sbase + (uint32_t)(row * (LDK * 2) + seg * 16);
        size_t oa = (size_t)row * sA + k0 + seg * 8;
        size_t ob = (size_t)row * sB + k0 + seg * 8;
        cp_async16(so,          Ah + oa);
        cp_async16(so + 10240u, Al + oa);
        cp_async16(so + 20480u, Bh + ob);
        cp_async16(so + 30720u, Bl + ob);
    }
}

// 3-pass bf16 compute of one 32-k chunk; warp tile 32(m) x 64(n)
__device__ __forceinline__ void mma_chunk3(uint32_t sb, int warp_m, int warp_n,
                                           uint32_t ldm_off, float acc[2][8][4]) {
    const uint32_t bAh = sb, bAl = sb + 10240, bBh = sb + 20480, bBl = sb + 30720;
#pragma unroll
    for (int ks = 0; ks < 32; ks += 16) {
        uint32_t aH[2][4], aL[2][4];
#pragma unroll
        for (int mt = 0; mt < 2; mt++) {
            uint32_t ro = (uint32_t)((warp_m * 32 + mt * 16) * LDK + ks) * 2 + ldm_off;
            LDM_X4(aH[mt], bAh + ro);
            LDM_X4(aL[mt], bAl + ro);
        }
#pragma unroll
        for (int c = 0; c < 4; c++) {
            uint32_t bh[4], bl[4];
            uint32_t ro = (uint32_t)((warp_n * 64 + c * 16) * LDK + ks) * 2 + ldm_off;
            LDM_X4(bh, bBh + ro);
            LDM_X4(bl, bBl + ro);
#pragma unroll
            for (int half = 0; half < 2; half++) {
                int nt = c * 2 + half;
                uint32_t bh0 = bh[half], bh1 = bh[half + 2];
                uint32_t bl0 = bl[half], bl1 = bl[half + 2];
#pragma unroll
                for (int mt = 0; mt < 2; mt++) {
                    mma_bf(acc[mt][nt], aH[mt], bh0, bh1);
                    mma_bf(acc[mt][nt], aH[mt], bl0, bl1);
                    mma_bf(acc[mt][nt], aL[mt], bh0, bh1);
                }
            }
        }
    }
}

// =====================================================================
// QKV projection: [8192,1024] @ w^T. Q/K tiles -> bf16 hi/lo; V -> fp16.
// =====================================================================
__global__ __launch_bounds__(256, 2) void qkv_gemm() {
    extern __shared__ char smem[];
    const uint32_t sb32 = smem_u32(smem);
    const int tid = threadIdx.x, lane = tid & 31, wid = tid >> 5;
    const int warp_m = wid & 3, warp_n = wid >> 2;
    const int g = lane >> 2, ti = lane & 3;
    const uint32_t ldm_off =
        (uint32_t)((((lane >> 3) & 1) * 8 + (lane & 7)) * LDK + ((lane >> 4) * 8)) * 2;
    const int bm = blockIdx.y * 128, bn = blockIdx.x * 128;
    const int K = DIMIN, N = QKV_COLS;

    const __nv_bfloat16* Ah0 = g_xh + (size_t)bm * K;
    const __nv_bfloat16* Al0 = g_xl + (size_t)bm * K;
    const __nv_bfloat16* Bh0 = g_wqh + (size_t)bn * K;
    const __nv_bfloat16* Bl0 = g_wql + (size_t)bn * K;

    float acc[2][8][4] = {};
    const int NT = K >> 5;

    stage_load(sb32, Ah0, Al0, K, Bh0, Bl0, K, 0, tid);
    CP_COMMIT();
    for (int kt = 0; kt < NT; kt++) {
        if (kt + 1 < NT) {
            stage_load(sb32 + ((kt + 1) & 1) * STG, Ah0, Al0, K, Bh0, Bl0, K,
                       (kt + 1) << 5, tid);
            CP_COMMIT();
            cp_wait<1>();
        } else {
            cp_wait<0>();
        }
        __syncthreads();
        mma_chunk3(sb32 + (kt & 1) * STG, warp_m, warp_n, ldm_off, acc);
        __syncthreads();
    }

    const bool isV = (bn >= 2 * HID);
#pragma unroll
    for (int mt = 0; mt < 2; mt++) {
        int r0 = bm + warp_m * 32 + mt * 16 + g;
#pragma unroll
        for (int nt = 0; nt < 8; nt++) {
            int col = bn + warp_n * 64 + nt * 8 + ti * 2;
            float v0 = acc[mt][nt][0], v1 = acc[mt][nt][1];
            float v2 = acc[mt][nt][2], v3 = acc[mt][nt][3];
            if (isV) {
                int cv = col - 2 * HID;
                __half2 w0; w0.x = __float2half(v0); w0.y = __float2half(v1);
                __half2 w1; w1.x = __float2half(v2); w1.y = __float2half(v3);
                *(__half2*)(g_v + (size_t)r0 * HID + cv)       = w0;
                *(__half2*)(g_v + (size_t)(r0 + 8) * HID + cv) = w1;
            } else {
                __nv_bfloat162 hp, lp;
                split2(v0, v1, hp, lp);
                *(__nv_bfloat162*)(g_qkvh + (size_t)r0 * N + col) = hp;
                *(__nv_bfloat162*)(g_qkvl + (size_t)r0 * N + col) = lp;
                split2(v2, v3, hp, lp);
                *(__nv_bfloat162*)(g_qkvh + (size_t)(r0 + 8) * N + col) = hp;
                *(__nv_bfloat162*)(g_qkvl + (size_t)(r0 + 8) * N + col) = lp;
            }
        }
    }
}

// =====================================================================
// scores: P = exp(scale*q.k) -> fp16; also per-tile column partial sums
// =====================================================================
__global__ __launch_bounds__(256, 2) void scores_mma() {
    extern __shared__ char smem[];
    const uint32_t sb32 = smem_u32(smem);
    const int tid = threadIdx.x, lane = tid & 31, wid = tid >> 5;
    const int warp_m = wid & 3, warp_n = wid >> 2;
    const int g = lane >> 2, ti = lane & 3;
    const uint32_t ldm_off =
        (uint32_t)((((lane >> 3) & 1) * 8 + (lane & 7)) * LDK + ((lane >> 4) * 8)) * 2;

    const int bh = blockIdx.z;
    const int b = bh >> 4, h = bh & 15;
    const int i0 = blockIdx.y * 128;
    const int j0 = blockIdx.x * 128;

    const size_t qoff = (size_t)(b * NSEQ) * QKV_COLS + h * DH;
    const __nv_bfloat16* Qh = g_qkvh + qoff + (size_t)i0 * QKV_COLS;
    const __nv_bfloat16* Ql = g_qkvl + qoff + (size_t)i0 * QKV_COLS;
    const __nv_bfloat16* Kh = g_qkvh + qoff + HID + (size_t)j0 * QKV_COLS;
    const __nv_bfloat16* Kl = g_qkvl + qoff + HID + (size_t)j0 * QKV_COLS;

    float acc[2][8][4] = {};

    stage_load(sb32, Qh, Ql, QKV_COLS, Kh, Kl, QKV_COLS, 0, tid);
    CP_COMMIT();
#pragma unroll
    for (int kt = 0; kt < 2; kt++) {
        if (kt == 0) {
            stage_load(sb32 + STG, Qh, Ql, QKV_COLS, Kh, Kl, QKV_COLS, 32, tid);
            CP_COMMIT();
            cp_wait<1>();
        } else {
            cp_wait<0>();
        }
        __syncthreads();
        mma_chunk3(sb32 + kt * STG, warp_m, warp_n, ldm_off, acc);
        __syncthreads();
    }

    __half* P = g_P + (size_t)bh * NSEQ * NSEQ;
    float cs[8][2];
#pragma unroll
    for (int nt = 0; nt < 8; nt++) { cs[nt][0] = 0.f; cs[nt][1] = 0.f; }

#pragma unroll
    for (int mt = 0; mt < 2; mt++) {
        int r0 = i0 + warp_m * 32 + mt * 16 + g;
#pragma unroll
        for (int nt = 0; nt < 8; nt++) {
            int col = j0 + warp_n * 64 + nt * 8 + ti * 2;
            __half h0 = __float2half(__expf(acc[mt][nt][0] * ATT_SCALE));
            __half h1 = __float2half(__expf(acc[mt][nt][1] * ATT_SCALE));
            __half h2 = __float2half(__expf(acc[mt][nt][2] * ATT_SCALE));
            __half h3 = __float2half(__expf(acc[mt][nt][3] * ATT_SCALE));
            cs[nt][0] += __half2float(h0) + __half2float(h2);
            cs[nt][1] += __half2float(h1) + __half2float(h3);
            __half2 w0; w0.x = h0; w0.y = h1;
            __half2 w1; w1.x = h2; w1.y = h3;
            *(__half2*)(P + (size_t)r0 * NSEQ + col)       = w0;
            *(__half2*)(P + (size_t)(r0 + 8) * NSEQ + col) = w1;
        }
    }

#pragma unroll
    for (int nt = 0; nt < 8; nt++) {
#pragma unroll
        for (int e = 0; e < 2; e++) {
            float v = cs[nt][e];
            v += __shfl_xor_sync(0xFFFFFFFF, v, 4);
            v += __shfl_xor_sync(0xFFFFFFFF, v, 8);
            v += __shfl_xor_sync(0xFFFFFFFF, v, 16);
            cs[nt][e] = v;
        }
    }
    float* spart = (float*)smem;
    if (g == 0) {
#pragma unroll
        for (int nt = 0; nt < 8; nt++) {
            spart[warp_m * 128 + warp_n * 64 + nt * 8 + ti * 2]     = cs[nt][0];
            spart[warp_m * 128 + warp_n * 64 + nt * 8 + ti * 2 + 1] = cs[nt][1];
        }
    }
    __syncthreads();
    if (tid < 128) {
        float s = spart[tid] + spart[128 + tid] + spart[256 + tid] + spart[384 + tid];
        g_pcs[((size_t)bh * NITILE + blockIdx.y) * NSEQ + j0 + tid] = s;
    }
}

// =====================================================================
// rsum: rl[bh][j] = 1 / sum_itile pcs
// =====================================================================
__global__ void rsum_kernel() {
    const int bh = blockIdx.y;
    const int j = blockIdx.x * 256 + threadIdx.x;
    const float* p = g_pcs + (size_t)bh * NITILE * NSEQ + j;
    float s = 0.f;
#pragma unroll
    for (int t = 0; t < NITILE; t++) s += p[(size_t)t * NSEQ];
    g_rl[bh * NSEQ + j] = 1.0f / s;
}

// =====================================================================
// av: Y = P_fp16 @ diag(rl) V_fp16   1-pass fp16.
// CTA tile 128(i) x 64(d), warp tile 16 x 64, k(j) chunk 32.
// =====================================================================
__global__ __launch_bounds__(256, 2) void av_mma() {
    __shared__ __align__(16) char sm[15360]; // P 10240 | V 5120
    const uint32_t smP = smem_u32(sm);
    const uint32_t smV = smP + 10240;
    char* smVc = sm + 10240;

    const int tid = threadIdx.x, lane = tid & 31, wid = tid >> 5;
    const int g = lane >> 2, ti = lane & 3;
    const uint32_t ldm_off =
        (uint32_t)((((lane >> 3) & 1) * 8 + (lane & 7)) * LDK + ((lane >> 4) * 8)) * 2;

    const int bh = blockIdx.y;
    const int b = bh >> 4, h = bh & 15;
    const int i0 = blockIdx.x * 128;

    const __half* Pg = g_P + (size_t)bh * NSEQ * NSEQ + (size_t)i0 * NSEQ;
    const __half* Vbase = g_v + (size_t)(b * NSEQ) * HID + h * DH;
    const float* rl = g_rl + bh * NSEQ;

    const int jl = tid >> 3;            // 0..31  (V row)
    const int d0 = (tid & 7) * 8;       // V col group

    float acc[8][4] = {};

    for (int j0 = 0; j0 < NSEQ; j0 += 32) {
        // P tile via cp.async: 128 rows x 32 j
#pragma unroll
        for (int r = 0; r < 2; r++) {
            int sid = tid + (r << 8);
            int row = sid >> 2, seg = sid & 3;
            uint32_t so = (uint32_t)(row * (LDK * 2) + seg * 16);
            cp_async16(smP + so, Pg + (size_t)row * NSEQ + j0 + seg * 8);
        }
        CP_COMMIT();
        // V tile: fp16 load, *rl, transpose into smem fp16
        {
            const float inv = rl[j0 + jl];
            const __half* Vr = Vbase + (size_t)(j0 + jl) * HID + d0;
            __half2 v4[4];
            *(float4*)v4 = *(const float4*)Vr;   // 8 halfs
#pragma unroll
            for (int e = 0; e < 4; e++) {
                float lo = __half2float(v4[e].x) * inv;
                float hi = __half2float(v4[e].y) * inv;
                int off0 = ((d0 + e * 2)     * LDK + jl) * 2;
                int off1 = ((d0 + e * 2 + 1) * LDK + jl) * 2;
                *(__half*)(smVc + off0) = __float2half(lo);
                *(__half*)(smVc + off1) = __float2half(hi);
            }
        }
        cp_wait<0>();
        __syncthreads();

#pragma unroll
        for (int ks = 0; ks < 32; ks += 16) {
            uint32_t aP[4];
            uint32_t ro = (uint32_t)((wid * 16) * LDK + ks) * 2 + ldm_off;
            LDM_X4(aP, smP + ro);
#pragma unroll
            for (int c = 0; c < 4; c++) {
                uint32_t bv[4];
                uint32_t rb = (uint32_t)((c * 16) * LDK + ks) * 2 + ldm_off;
                LDM_X4(bv, smV + rb);
#pragma unroll
                for (int half = 0; half < 2; half++)
                    mma_f16(acc[c * 2 + half], aP, bv[half], bv[half + 2]);
            }
        }
        __syncthreads();
    }

    // epilogue: write y fp16
    const int irow = i0 + wid * 16 + g;
#pragma unroll
    for (int nt = 0; nt < 8; nt++) {
        int d = nt * 8 + ti * 2;
        size_t o0 = (size_t)(b * NSEQ + irow) * HID + h * DH + d;
        size_t o1 = (size_t)(b * NSEQ + irow + 8) * HID + h * DH + d;
        __half2 w0; w0.x = __float2half(acc[nt][0]); w0.y = __float2half(acc[nt][1]);
        __half2 w1; w1.x = __float2half(acc[nt][2]); w1.y = __float2half(acc[nt][3]);
        *(__half2*)(g_y + o0) = w0;
        *(__half2*)(g_y + o1) = w1;
    }
}

// =====================================================================
// out-proj: out[M,N] = y_fp16[M,K] @ (w_out^T fp16 hi/lo [N,K])^T + bias
// 2-pass fp16. Stage: A 10240 | Bh 10240 | Bl 10240 ; stage 30720.
// out/bias passed as kernel PARAMETERS (graph-capture-safe).
// =====================================================================
#define OSTG 30720
#define ODSMEM (2*OSTG)

__global__ __launch_bounds__(256, 2) void out_gemm(float* __restrict__ C,
                                                   const float* __restrict__ bias) {
    extern __shared__ char smem[];
    const uint32_t sb32 = smem_u32(smem);
    const int tid = threadIdx.x, lane = tid & 31, wid = tid >> 5;
    const int warp_m = wid & 3, warp_n = wid >> 2;
    const int g = lane >> 2, ti = lane & 3;
    const uint32_t ldm_off =
        (uint32_t)((((lane >> 3) & 1) * 8 + (lane & 7)) * LDK + ((lane >> 4) * 8)) * 2;
    const int bm = blockIdx.y * 128, bn = blockIdx.x * 128;
    const int K = HID, N = DIMIN;

    const __half* A0  = g_y   + (size_t)bm * K;
    const __half* Bh0 = g_woh + (size_t)bn * K;
    const __half* Bl0 = g_wol + (size_t)bn * K;

    float acc[2][8][4] = {};
    const int NT = K >> 5;

    auto stage = [&](uint32_t sbase, int k0) {
#pragma unroll
        for (int r = 0; r < 2; r++) {
            int sid = tid + (r << 8);
            int row = sid >> 2, seg = sid & 3;
            uint32_t so = sbase + (uint32_t)(row * (LDK * 2) + seg * 16);
            size_t oa = (size_t)row * K + k0 + seg * 8;
            cp_async16(so,          A0  + oa);
            cp_async16(so + 10240u, Bh0 + oa);
            cp_async16(so + 20480u, Bl0 + oa);
        }
    };

    stage(sb32, 0);
    CP_COMMIT();
    for (int kt = 0; kt < NT; kt++) {
        if (kt + 1 < NT) {
            stage(sb32 + ((kt + 1) & 1) * OSTG, (kt + 1) << 5);
            CP_COMMIT();
            cp_wait<1>();
        } else {
            cp_wait<0>();
        }
        __syncthreads();
        const uint32_t sb = sb32 + (kt & 1) * OSTG;
        const uint32_t bA = sb, bBh = sb + 10240, bBl = sb + 20480;
#pragma unroll
        for (int ks = 0; ks < 32; ks += 16) {
            uint32_t aF[2][4];
#pragma unroll
            for (int mt = 0; mt < 2; mt++) {
                uint32_t ro = (uint32_t)((warp_m * 32 + mt * 16) * LDK + ks) * 2 + ldm_off;
                LDM_X4(aF[mt], bA + ro);
            }
#pragma unroll
            for (int c = 0; c < 4; c++) {
                uint32_t bh[4], bl[4];
                uint32_t ro = (uint32_t)((warp_n * 64 + c * 16) * LDK + ks) * 2 + ldm_off;
                LDM_X4(bh, bBh + ro);
                LDM_X4(bl, bBl + ro);
#pragma unroll
                for (int half = 0; half < 2; half++) {
                    int nt = c * 2 + half;
#pragma unroll
                    for (int mt = 0; mt < 2; mt++) {
                        mma_f16(acc[mt][nt], aF[mt], bh[half], bh[half + 2]);
                        mma_f16(acc[mt][nt], aF[mt], bl[half], bl[half + 2]);
                    }
                }
            }
        }
        __syncthreads();
    }

#pragma unroll
    for (int mt = 0; mt < 2; mt++) {
        int r0 = bm + warp_m * 32 + mt * 16 + g;
#pragma unroll
        for (int nt = 0; nt < 8; nt++) {
            int col = bn + warp_n * 64 + nt * 8 + ti * 2;
            float2 bb = *(const float2*)(bias + col);
            *(float2*)(C + (size_t)r0 * N + col) =
                make_float2(acc[mt][nt][0] + bb.x, acc[mt][nt][1] + bb.y);
            *(float2*)(C + (size_t)(r0 + 8) * N + col) =
                make_float2(acc[mt][nt][2] + bb.x, acc[mt][nt][3] + bb.y);
        }
    }
}

// =====================================================================
// split fp32 -> bf16 hi/lo (elementwise)
// =====================================================================
__global__ void split_kernel(const float* __restrict__ in,
                             __nv_bfloat16* __restrict__ hi,
                             __nv_bfloat16* __restrict__ lo, size_t n4) {
    size_t i = (size_t)blockIdx.x * blockDim.x + threadIdx.x;
    if (i >= n4) return;
    float4 v = ((const float4*)in)[i];
    __nv_bfloat162 hp0, hp1, lp0, lp1;
    split2(v.x, v.y, hp0, lp0);
    split2(v.z, v.w, hp1, lp1);
    ((__nv_bfloat162*)hi)[i * 2 + 0] = hp0;
    ((__nv_bfloat162*)hi)[i * 2 + 1] = hp1;
    ((__nv_bfloat162*)lo)[i * 2 + 0] = lp0;
    ((__nv_bfloat162*)lo)[i * 2 + 1] = lp1;
}

// =====================================================================
// transpose + split: w[K,N] fp32 -> th/tl [N,K] bf16
// =====================================================================
__global__ void transpose_split_kernel(const float* __restrict__ w,
                                       __nv_bfloat16* __restrict__ th,
                                       __nv_bfloat16* __restrict__ tl,
                                       int K, int N) {
    __shared__ float tile[32][33];
    const int k0 = blockIdx.y * 32;
    const int n0 = blockIdx.x * 32;
    const int tx = threadIdx.x, ty = threadIdx.y;   // (32,8)
#pragma unroll
    for (int r = 0; r < 4; r++)
        tile[ty + 8 * r][tx] = w[(size_t)(k0 + ty + 8 * r) * N + n0 + tx];
    __syncthreads();
#pragma unroll
    for (int r = 0; r < 4; r++) {
        const int n = n0 + ty + 8 * r;
        const int k = k0 + tx;
        float v = tile[tx][ty + 8 * r];
        __nv_bfloat16 hh = __float2bfloat16(v);
        th[(size_t)n * K + k] = hh;
        tl[(size_t)n * K + k] = __float2bfloat16(v - __bfloat162float(hh));
    }
}

// transpose + split to fp16 hi/lo (for w_out)
__global__ void transpose_split_f16(const float* __restrict__ w,
                                    __half* __restrict__ th,
                                    __half* __restrict__ tl,
                                    int K, int N) {
    __shared__ float tile[32][33];
    const int k0 = blockIdx.y * 32;
    const int n0 = blockIdx.x * 32;
    const int tx = threadIdx.x, ty = threadIdx.y;   // (32,8)
#pragma unroll
    for (int r = 0; r < 4; r++)
        tile[ty + 8 * r][tx] = w[(size_t)(k0 + ty + 8 * r) * N + n0 + tx];
    __syncthreads();
#pragma unroll
    for (int r = 0; r < 4; r++) {
        const int n = n0 + ty + 8 * r;
        const int k = k0 + tx;
        float v = tile[tx][ty + 8 * r];
        __half hh = __float2half(v);
        th[(size_t)n * K + k] = hh;
        tl[(size_t)n * K + k] = __float2half(v - __half2float(hh));
    }
}

// ---------------------------------------------------------------------
extern "C" void kernel_launch(void* const* d_in, const int* in_sizes, int n_in,
                              void* d_out, int out_size) {
    const float* x     = (const float*)d_in[0];
    const float* w_qkv = (const float*)d_in[1];
    const float* w_out = (const float*)d_in[2];
    const float* b_out = (const float*)d_in[3];
    float* out = (float*)d_out;

    cudaFuncSetAttribute(qkv_gemm,
                         cudaFuncAttributeMaxDynamicSharedMemorySize, DSMEM);
    cudaFuncSetAttribute(scores_mma,
                         cudaFuncAttributeMaxDynamicSharedMemorySize, DSMEM);
    cudaFuncSetAttribute(out_gemm,
                         cudaFuncAttributeMaxDynamicSharedMemorySize, ODSMEM);

    void *p_xh, *p_xl, *p_wqh, *p_wql, *p_woh, *p_wol;
    cudaGetSymbolAddress(&p_xh,  g_xh);
    cudaGetSymbolAddress(&p_xl,  g_xl);
    cudaGetSymbolAddress(&p_wqh, g_wqh);
    cudaGetSymbolAddress(&p_wql, g_wql);
    cudaGetSymbolAddress(&p_woh, g_woh);
    cudaGetSymbolAddress(&p_wol, g_wol);

    // 0a. split x -> bf16 hi/lo
    {
        size_t n4 = (size_t)ROWS * DIMIN / 4;
        split_kernel<<<(unsigned)((n4 + 255) / 256), 256>>>(
            x, (__nv_bfloat16*)p_xh, (__nv_bfloat16*)p_xl, n4);
    }
    // 0b. transpose+split w_qkv -> bf16 [N,K]
    transpose_split_kernel<<<dim3(QKV_COLS / 32, DIMIN / 32), dim3(32, 8)>>>(
        w_qkv, (__nv_bfloat16*)p_wqh, (__nv_bfloat16*)p_wql, DIMIN, QKV_COLS);
    // 0c. transpose+split w_out -> fp16 [N,K]
    transpose_split_f16<<<dim3(HID / 32, DIMIN / 32), dim3(32, 8)>>>(
        w_out, (__half*)p_woh, (__half*)p_wol, DIMIN, HID);

    // 1. QKV projection: Q/K -> bf16 hi/lo, V -> fp16
    qkv_gemm<<<dim3(QKV_COLS / 128, ROWS / 128), 256, DSMEM>>>();

    // 2. P = exp(scale * Q K^T) (fp16) + partial column sums
    scores_mma<<<dim3(NSEQ / 128, NSEQ / 128, BH), 256, DSMEM>>>();

    // 3. rl = 1 / column sums
    rsum_kernel<<<dim3(NSEQ / 256, BH), 256>>>();

    // 4. Y = P diag(rl) V  -> y fp16
    av_mma<<<dim3(NSEQ / 128, BH), 256>>>();

    // 5. out = Y @ w_out + b_out (2-pass fp16)
    out_gemm<<<dim3(HID / 128, ROWS / 128), 256, ODSMEM>>>(out, b_out);
}